// round 4
// baseline (speedup 1.0000x reference)
#include <cuda_runtime.h>

// LiquidNeuralNetwork B=256,S=4096,I=32,H=64,O=1 — latency-optimized scan.
//
// Algebra: Wc = W_ih@W_in (64x32), cbias = bias + W_ih@b_in
//   z_t   = tanh(h_t)@W_hh^T + x_t@Wc^T + cbias
//   h_t+1 = h_t + (z_t - h_t)/tau          (dt=1)
//   out_t = tanh(h_t+1)@W_out^T + b_out
//
// Mapping: 1 CTA / batch chain, 128 threads. Thread (j = tid>>1, p = tid&1)
// owns half of hidden unit j's dot products, packed as f32x2 K-pairs:
// 16 FFMA2 (hh) on the serial path + 8 FFMA2 (x·Wc) computed in the shadow
// of the previous step. Halves combined with one SHFL.BFLY(1) (same warp).
// tanh via exp2-based formula (2 MUFU) instead of tanhf.

#define NB   256
#define SEQ  4096
#define NI   32
#define NH   64
#define TC   64
#define RS   68            // th ring row stride (floats): 16B-aligned, bank-spread
#define NC   (SEQ / TC)

typedef unsigned long long u64;

__device__ __forceinline__ u64 pk2(float lo, float hi) {
    u64 r; asm("mov.b64 %0, {%1,%2};" : "=l"(r) : "f"(lo), "f"(hi)); return r;
}
__device__ __forceinline__ float2 upk2(u64 v) {
    float2 f; asm("mov.b64 {%0,%1}, %2;" : "=f"(f.x), "=f"(f.y) : "l"(v)); return f;
}
__device__ __forceinline__ u64 fma2(u64 a, u64 b, u64 c) {
    u64 d; asm("fma.rn.f32x2 %0, %1, %2, %3;" : "=l"(d) : "l"(a), "l"(b), "l"(c)); return d;
}
__device__ __forceinline__ u64 add2(u64 a, u64 b) {
    u64 d; asm("add.rn.f32x2 %0, %1, %2;" : "=l"(d) : "l"(a), "l"(b)); return d;
}

__device__ float g_Wc[NH * NI];
__device__ float g_cbias[NH];

__global__ void precompute_kernel(const float* __restrict__ W_in,
                                  const float* __restrict__ b_in,
                                  const float* __restrict__ W_ih,
                                  const float* __restrict__ bias)
{
    const int g = threadIdx.x;
    if (g >= NH) return;
    float wih[NH];
#pragma unroll
    for (int h = 0; h < NH; h++) wih[h] = W_ih[g * NH + h];
#pragma unroll 4
    for (int i = 0; i < NI; i++) {
        float s0 = 0.f, s1 = 0.f;
#pragma unroll
        for (int h = 0; h < NH; h += 2) {
            s0 += wih[h + 0] * W_in[(h + 0) * NI + i];
            s1 += wih[h + 1] * W_in[(h + 1) * NI + i];
        }
        g_Wc[g * NI + i] = s0 + s1;
    }
    float cb = bias[g];
#pragma unroll
    for (int h = 0; h < NH; h++) cb += wih[h] * b_in[h];
    g_cbias[g] = cb;
}

__global__ __launch_bounds__(128) void lnn_scan_kernel(
    const float* __restrict__ x,
    const float* __restrict__ W_hh,
    const float* __restrict__ tau,
    const float* __restrict__ W_out,
    const float* __restrict__ b_out,
    float* __restrict__ out)
{
    __shared__ __align__(16) float sh_th[(TC + 1) * RS];   // tanh history ring
    __shared__ __align__(16) float sh_x[(TC + 1) * NI];    // x chunk (+1 garbage row)
    __shared__ float sh_wo[NH];

    const int tid = threadIdx.x;
    const int j   = tid >> 1;      // hidden unit
    const int p   = tid & 1;       // which half of the dot product
    const int b   = blockIdx.x;

    // Packed resident weights: half p covers k in [32p,32p+32) (hh), [16p,16p+16) (x)
    u64 Whh2[16], Wc2[8];
    {
        const float* wr = W_hh + j * NH + 32 * p;
#pragma unroll
        for (int m = 0; m < 16; m++) Whh2[m] = pk2(wr[2 * m], wr[2 * m + 1]);
        const float* wc = g_Wc + j * NI + 16 * p;
#pragma unroll
        for (int m = 0; m < 8; m++) Wc2[m] = pk2(wc[2 * m], wc[2 * m + 1]);
    }
    const float cb   = g_cbias[j];
    const float invt = 1.0f / tau[j];
    const float bo   = b_out[0];
    if (tid < NH) sh_wo[tid] = W_out[tid];

    const float4* xg = (const float4*)(x + (size_t)b * SEQ * NI);  // 512 float4/chunk
    float* outb = out + (size_t)b * SEQ;

    float4 pf[4];
#pragma unroll
    for (int q = 0; q < 4; q++) pf[q] = xg[q * 128 + tid];

    float h = 0.f, th = 0.f;

    for (int c = 0; c < NC; c++) {
        // Commit prefetched x chunk; seed ring row 0; prefetch next chunk.
#pragma unroll
        for (int q = 0; q < 4; q++) ((float4*)sh_x)[q * 128 + tid] = pf[q];
        if (p == 0) sh_th[j] = th;
        if (c + 1 < NC) {
#pragma unroll
            for (int q = 0; q < 4; q++) pf[q] = xg[(c + 1) * 512 + q * 128 + tid];
        }
        __syncthreads();   // sh_x (and sh_wo on first pass) visible

        // x-projection partial for tt = 0
        u64 xz0 = 0ull, xz1 = 0ull;
        {
            const float4* x4 = (const float4*)(sh_x + 16 * p);
#pragma unroll
            for (int m = 0; m < 4; m++) {
                float4 v = x4[m];
                xz0 = fma2(pk2(v.x, v.y), Wc2[2 * m + 0], xz0);
                xz1 = fma2(pk2(v.z, v.w), Wc2[2 * m + 1], xz1);
            }
        }

#pragma unroll 1
        for (int tt = 0; tt < TC; tt++) {
            __syncthreads();   // ring row tt visible

            // hh half-dot: 32 terms = 16 FFMA2, 4 accumulator chains
            u64 a0 = 0ull, a1 = 0ull, a2 = 0ull, a3 = 0ull;
            const float4* t4 = (const float4*)(sh_th + tt * RS + 32 * p);
#pragma unroll
            for (int m = 0; m < 8; m += 2) {
                float4 v = t4[m];
                float4 w = t4[m + 1];
                a0 = fma2(pk2(v.x, v.y), Whh2[2 * m + 0], a0);
                a1 = fma2(pk2(v.z, v.w), Whh2[2 * m + 1], a1);
                a2 = fma2(pk2(w.x, w.y), Whh2[2 * m + 2], a2);
                a3 = fma2(pk2(w.z, w.w), Whh2[2 * m + 3], a3);
            }
            a0 = add2(a0, a1); a2 = add2(a2, a3); xz0 = add2(xz0, xz1);
            a0 = add2(a0, a2); a0 = add2(a0, xz0);
            float2 f = upk2(a0);
            float part  = f.x + f.y;
            float other = __shfl_xor_sync(0xFFFFFFFFu, part, 1);  // partner half
            float z = (part + other) + cb;

            h = fmaf(z - h, invt, h);                  // Euler step (dt = 1)
            float e = __expf(h + h);                   // tanh = 1 - 2/(e^{2h}+1)
            th = 1.f - __fdividef(2.f, e + 1.f);
            if (p == 0) sh_th[(tt + 1) * RS + j] = th; // fresh row, no WAR

            // Shadow-compute x-projection for tt+1 (tt=63 reads the unused
            // extra sh_x row; result is discarded — xz is reset at chunk top).
            const float4* nx4 = (const float4*)(sh_x + (tt + 1) * NI + 16 * p);
            xz0 = 0ull; xz1 = 0ull;
#pragma unroll
            for (int m = 0; m < 4; m++) {
                float4 v = nx4[m];
                xz0 = fma2(pk2(v.x, v.y), Wc2[2 * m + 0], xz0);
                xz1 = fma2(pk2(v.z, v.w), Wc2[2 * m + 1], xz1);
            }
        }
        __syncthreads();   // ring rows 1..TC complete

        // Output head, batched per chunk: thread tt computes out[c*TC+tt]
        if (tid < TC) {
            const float* row = sh_th + (tid + 1) * RS;
            float o0 = bo, o1 = 0.f, o2 = 0.f, o3 = 0.f;
#pragma unroll
            for (int k = 0; k < NH; k += 4) {
                o0 += row[k + 0] * sh_wo[k + 0];
                o1 += row[k + 1] * sh_wo[k + 1];
                o2 += row[k + 2] * sh_wo[k + 2];
                o3 += row[k + 3] * sh_wo[k + 3];
            }
            outb[c * TC + tid] = (o0 + o1) + (o2 + o3);
        }
        // No barrier: next chunk writes only sh_x / ring row 0 before its
        // first __syncthreads, disjoint from rows 1..TC read here.
    }
}

extern "C" void kernel_launch(void* const* d_in, const int* in_sizes, int n_in,
                              void* d_out, int out_size)
{
    const float* x     = (const float*)d_in[0];
    const float* W_in  = (const float*)d_in[1];
    const float* b_in  = (const float*)d_in[2];
    const float* W_hh  = (const float*)d_in[3];
    const float* W_ih  = (const float*)d_in[4];
    const float* bias  = (const float*)d_in[5];
    const float* tau   = (const float*)d_in[6];
    const float* W_out = (const float*)d_in[7];
    const float* b_out = (const float*)d_in[8];
    float* out = (float*)d_out;

    precompute_kernel<<<1, 64>>>(W_in, b_in, W_ih, bias);
    lnn_scan_kernel<<<NB, 128>>>(x, W_hh, tau, W_out, b_out, out);
}

// round 5
// speedup vs baseline: 1.2247x; 1.2247x over previous
#include <cuda_runtime.h>

// LiquidNeuralNetwork B=256,S=4096,I=32,H=64,O=1 — latency-optimized scan, v5.
//
// Algebra: Wc = W_ih@W_in (64x32), cbias = bias + W_ih@b_in
//   z_t   = tanh(h_t)@W_hh^T + x_t@Wc^T + cbias
//   h_t+1 = h_t + (z_t - h_t)/tau          (dt=1)
//   out_t = tanh(h_t+1)@W_out^T + b_out
//
// Mapping: 128 CTAs (< 148 SMs -> one CTA per SM, no FFMA-pipe sharing),
// 2 chains per CTA, 64 threads per chain (one warp per SMSP). Thread j owns
// h[j]; dot products as true FFMA2: shared is read as ulonglong2 (f32x2 pairs
// directly from LDS.128, zero pack movs), weights pre-packed in registers.
// Recurrent tanh = tanh.approx.f32 (error damped by ||W_hh||~0.08 before
// re-entering); output head uses exact exp-based tanh on stored h rows,
// computed off the serial path in a batched per-chunk pass.

#define NB   256
#define SEQ  4096
#define NI   32
#define NH   64
#define TC   32
#define NC   (SEQ / TC)
#define RS   68            // tanh ring row stride (16B-aligned)
#define HS   65            // h-buffer row stride (conflict-free transposed access)

typedef unsigned long long u64;

__device__ __forceinline__ float2 upk2(u64 v) {
    float2 f; asm("mov.b64 {%0,%1}, %2;" : "=f"(f.x), "=f"(f.y) : "l"(v)); return f;
}
__device__ __forceinline__ u64 pk2(float lo, float hi) {
    u64 r; asm("mov.b64 %0, {%1,%2};" : "=l"(r) : "f"(lo), "f"(hi)); return r;
}
__device__ __forceinline__ u64 fma2(u64 a, u64 b, u64 c) {
    u64 d; asm("fma.rn.f32x2 %0, %1, %2, %3;" : "=l"(d) : "l"(a), "l"(b), "l"(c)); return d;
}
__device__ __forceinline__ u64 add2(u64 a, u64 b) {
    u64 d; asm("add.rn.f32x2 %0, %1, %2;" : "=l"(d) : "l"(a), "l"(b)); return d;
}
__device__ __forceinline__ float tanh_fast(float x) {
    float y; asm("tanh.approx.f32 %0, %1;" : "=f"(y) : "f"(x)); return y;
}
__device__ __forceinline__ float tanh_exact(float x) {
    float e = __expf(x + x);               // saturates correctly at +/-1
    return 1.0f - __fdividef(2.0f, e + 1.0f);
}

__device__ float g_Wc[NH * NI];
__device__ float g_cbias[NH];

__global__ void precompute_kernel(const float* __restrict__ W_in,
                                  const float* __restrict__ b_in,
                                  const float* __restrict__ W_ih,
                                  const float* __restrict__ bias)
{
    const int g = threadIdx.x;
    if (g >= NH) return;
    float wih[NH];
#pragma unroll
    for (int h = 0; h < NH; h++) wih[h] = W_ih[g * NH + h];
#pragma unroll 4
    for (int i = 0; i < NI; i++) {
        float s0 = 0.f, s1 = 0.f;
#pragma unroll
        for (int h = 0; h < NH; h += 2) {
            s0 += wih[h + 0] * W_in[(h + 0) * NI + i];
            s1 += wih[h + 1] * W_in[(h + 1) * NI + i];
        }
        g_Wc[g * NI + i] = s0 + s1;
    }
    float cb = bias[g];
#pragma unroll
    for (int h = 0; h < NH; h++) cb += wih[h] * b_in[h];
    g_cbias[g] = cb;
}

__global__ __launch_bounds__(128) void lnn_scan_kernel(
    const float* __restrict__ x,
    const float* __restrict__ W_hh,
    const float* __restrict__ tau,
    const float* __restrict__ W_out,
    const float* __restrict__ b_out,
    float* __restrict__ out)
{
    __shared__ __align__(16) float sh_th[2][(TC + 1) * RS];  // tanh ring
    __shared__ __align__(16) float sh_h [2][(TC + 1) * HS];  // raw h (for exact head)
    __shared__ __align__(16) float sh_x [2][(TC + 1) * NI];  // x chunk (+1 shadow row)
    __shared__ float sh_wo[NH];

    const int tid = threadIdx.x;
    const int ch  = tid >> 6;          // chain within CTA (0/1)
    const int lid = tid & 63;          // hidden unit j this thread owns
    const int b   = blockIdx.x * 2 + ch;

    // Pre-packed resident weights: 32 f32x2 hh-pairs + 16 f32x2 x-pairs
    u64 Whh2[NH / 2], Wc2[NI / 2];
    {
        const float* wr = W_hh + lid * NH;
#pragma unroll
        for (int m = 0; m < NH / 2; m++) Whh2[m] = pk2(wr[2 * m], wr[2 * m + 1]);
        const float* wc = g_Wc + lid * NI;
#pragma unroll
        for (int m = 0; m < NI / 2; m++) Wc2[m] = pk2(wc[2 * m], wc[2 * m + 1]);
    }
    const float cb   = g_cbias[lid];
    const float invt = 1.0f / tau[lid];
    const float bo   = b_out[0];
    if (tid < NH) sh_wo[tid] = W_out[tid];

    const float4* xg = (const float4*)(x + (size_t)b * SEQ * NI);  // 256 float4/chunk
    float* outb = out + (size_t)b * SEQ;

    float4 pf[4];
#pragma unroll
    for (int q = 0; q < 4; q++) pf[q] = xg[q * 64 + lid];

    float h = 0.f, th = 0.f;

#pragma unroll 1
    for (int c = 0; c < NC; c++) {
        // Commit prefetched x chunk; seed ring row 0; prefetch next chunk.
#pragma unroll
        for (int q = 0; q < 4; q++) ((float4*)sh_x[ch])[q * 64 + lid] = pf[q];
        sh_th[ch][lid] = th;
        if (c + 1 < NC) {
#pragma unroll
            for (int q = 0; q < 4; q++) pf[q] = xg[(c + 1) * 256 + q * 64 + lid];
        }
        __syncthreads();   // sh_x / ring row 0 (and sh_wo first pass) visible

        // x-projection partial for tt = 0 (16 FFMA2)
        u64 xz0 = 0ull, xz1 = 0ull;
        {
            const ulonglong2* x2 = (const ulonglong2*)(sh_x[ch]);
#pragma unroll
            for (int m = 0; m < 8; m++) {
                ulonglong2 v = x2[m];
                xz0 = fma2(v.x, Wc2[2 * m + 0], xz0);
                xz1 = fma2(v.y, Wc2[2 * m + 1], xz1);
            }
        }

#pragma unroll 1
        for (int tt = 0; tt < TC; tt++) {
            __syncthreads();   // ring row tt visible

            // hh dot: 64 terms = 32 FFMA2 over 4 accumulator chains,
            // x partial folded into chains 0/1.
            u64 a0 = xz0, a1 = xz1, a2 = 0ull, a3 = 0ull;
            const ulonglong2* t2 = (const ulonglong2*)(sh_th[ch] + tt * RS);
#pragma unroll
            for (int m = 0; m < 16; m += 2) {
                ulonglong2 v = t2[m];
                ulonglong2 w = t2[m + 1];
                a0 = fma2(v.x, Whh2[2 * m + 0], a0);
                a1 = fma2(v.y, Whh2[2 * m + 1], a1);
                a2 = fma2(w.x, Whh2[2 * m + 2], a2);
                a3 = fma2(w.y, Whh2[2 * m + 3], a3);
            }
            a0 = add2(a0, a1); a2 = add2(a2, a3); a0 = add2(a0, a2);
            float2 f = upk2(a0);
            const float z = (f.x + f.y) + cb;

            h  = fmaf(z - h, invt, h);                 // Euler step (dt = 1)
            th = tanh_fast(h);                         // MUFU.TANH (recurrence only)
            sh_th[ch][(tt + 1) * RS + lid] = th;       // fresh rows, no WAR
            sh_h [ch][(tt + 1) * HS + lid] = h;

            // Shadow x-projection for tt+1 (tt=TC-1 reads the spare row;
            // discarded — xz reset at next chunk top).
            const ulonglong2* nx2 = (const ulonglong2*)(sh_x[ch] + (tt + 1) * NI);
            xz0 = 0ull; xz1 = 0ull;
#pragma unroll
            for (int m = 0; m < 8; m++) {
                ulonglong2 v = nx2[m];
                xz0 = fma2(v.x, Wc2[2 * m + 0], xz0);
                xz1 = fma2(v.y, Wc2[2 * m + 1], xz1);
            }
        }
        __syncthreads();   // all rows 1..TC complete

        // Output head (off-path, exact):
        // Phase A: column-wise exact tanh of h rows (conflict-free: (r+j)%32).
#pragma unroll 4
        for (int r = 1; r <= TC; r++) {
            float* p = sh_h[ch] + r * HS + lid;
            *p = tanh_exact(*p);
        }
        __syncthreads();

        // Phase B: thread tt<TC computes out[c*TC+tt] (banks (lid+1+k)%32, clean).
        if (lid < TC) {
            const float* row = sh_h[ch] + (lid + 1) * HS;
            float o0 = bo, o1 = 0.f, o2 = 0.f, o3 = 0.f;
#pragma unroll
            for (int k = 0; k < NH; k += 4) {
                o0 += row[k + 0] * sh_wo[k + 0];
                o1 += row[k + 1] * sh_wo[k + 1];
                o2 += row[k + 2] * sh_wo[k + 2];
                o3 += row[k + 3] * sh_wo[k + 3];
            }
            outb[c * TC + lid] = (o0 + o1) + (o2 + o3);
        }
        // No trailing barrier: next chunk's pre-barrier writes touch only
        // sh_x and ring row 0, which Phase B does not read.
    }
}

extern "C" void kernel_launch(void* const* d_in, const int* in_sizes, int n_in,
                              void* d_out, int out_size)
{
    const float* x     = (const float*)d_in[0];
    const float* W_in  = (const float*)d_in[1];
    const float* b_in  = (const float*)d_in[2];
    const float* W_hh  = (const float*)d_in[3];
    const float* W_ih  = (const float*)d_in[4];
    const float* bias  = (const float*)d_in[5];
    const float* tau   = (const float*)d_in[6];
    const float* W_out = (const float*)d_in[7];
    const float* b_out = (const float*)d_in[8];
    float* out = (float*)d_out;

    precompute_kernel<<<1, 64>>>(W_in, b_in, W_ih, bias);
    lnn_scan_kernel<<<NB / 2, 128>>>(x, W_hh, tau, W_out, b_out, out);
}

// round 6
// speedup vs baseline: 1.3825x; 1.1288x over previous
#include <cuda_runtime.h>

// LiquidNeuralNetwork B=256,S=4096,I=32,H=64,O=1 — v6: decoupled chains,
// named per-chain barriers, approx-tanh ring feeds head directly.
//
// Algebra: Wc = W_ih@W_in (64x32), cbias = bias + W_ih@b_in
//   z_t   = tanh(h_t)@W_hh^T + x_t@Wc^T + cbias
//   h_t+1 = h_t + (z_t - h_t)/tau  =  (1-1/tau)*h_t + (1/tau)*z_t
//   out_t = tanh(h_t+1)@W_out^T + b_out
//
// Mapping: 128 CTAs, 2 independent chains per CTA, 64 threads per chain
// (thread j owns hidden unit j; 2 warps per chain, one per SMSP). The two
// chains NEVER synchronize with each other: every barrier is a named
// bar.sync(1+ch, 64). tanh history ring in shared; FFMA2 dot products with
// ulonglong2 shared loads; x-projection shadow-computed off the h-chain;
// output head batched per chunk from the ring.

#define NB   256
#define SEQ  4096
#define NI   32
#define NH   64
#define TC   32
#define NC   (SEQ / TC)
#define RS   68            // ring row stride: 16B-aligned for LDS.128

typedef unsigned long long u64;

__device__ __forceinline__ float2 upk2(u64 v) {
    float2 f; asm("mov.b64 {%0,%1}, %2;" : "=f"(f.x), "=f"(f.y) : "l"(v)); return f;
}
__device__ __forceinline__ u64 pk2(float lo, float hi) {
    u64 r; asm("mov.b64 %0, {%1,%2};" : "=l"(r) : "f"(lo), "f"(hi)); return r;
}
__device__ __forceinline__ u64 fma2(u64 a, u64 b, u64 c) {
    u64 d; asm("fma.rn.f32x2 %0, %1, %2, %3;" : "=l"(d) : "l"(a), "l"(b), "l"(c)); return d;
}
__device__ __forceinline__ u64 add2(u64 a, u64 b) {
    u64 d; asm("add.rn.f32x2 %0, %1, %2;" : "=l"(d) : "l"(a), "l"(b)); return d;
}
__device__ __forceinline__ float tanh_fast(float x) {
    float y; asm("tanh.approx.f32 %0, %1;" : "=f"(y) : "f"(x)); return y;
}
__device__ __forceinline__ void chain_bar(int ch) {
    asm volatile("bar.sync %0, 64;" :: "r"(1 + ch) : "memory");
}

__device__ float g_Wc[NH * NI];
__device__ float g_cbias[NH];

__global__ void precompute_kernel(const float* __restrict__ W_in,
                                  const float* __restrict__ b_in,
                                  const float* __restrict__ W_ih,
                                  const float* __restrict__ bias)
{
    const int g = threadIdx.x;
    if (g >= NH) return;
    float wih[NH];
#pragma unroll
    for (int h = 0; h < NH; h++) wih[h] = W_ih[g * NH + h];
#pragma unroll 4
    for (int i = 0; i < NI; i++) {
        float s0 = 0.f, s1 = 0.f;
#pragma unroll
        for (int h = 0; h < NH; h += 2) {
            s0 += wih[h + 0] * W_in[(h + 0) * NI + i];
            s1 += wih[h + 1] * W_in[(h + 1) * NI + i];
        }
        g_Wc[g * NI + i] = s0 + s1;
    }
    float cb = bias[g];
#pragma unroll
    for (int h = 0; h < NH; h++) cb += wih[h] * b_in[h];
    g_cbias[g] = cb;
}

__global__ __launch_bounds__(128) void lnn_scan_kernel(
    const float* __restrict__ x,
    const float* __restrict__ W_hh,
    const float* __restrict__ tau,
    const float* __restrict__ W_out,
    const float* __restrict__ b_out,
    float* __restrict__ out)
{
    __shared__ __align__(16) float sh_th[2][(TC + 1) * RS];  // tanh history ring
    __shared__ __align__(16) float sh_x [2][(TC + 1) * NI];  // x chunk (+1 shadow row)
    __shared__ float sh_wo[2][NH];                           // per-chain copy of W_out

    const int tid = threadIdx.x;
    const int ch  = tid >> 6;          // chain within CTA (fully independent)
    const int lid = tid & 63;          // hidden unit this thread owns
    const int b   = blockIdx.x * 2 + ch;

    // Pre-packed resident weights
    u64 Whh2[NH / 2], Wc2[NI / 2];
    {
        const float* wr = W_hh + lid * NH;
#pragma unroll
        for (int m = 0; m < NH / 2; m++) Whh2[m] = pk2(wr[2 * m], wr[2 * m + 1]);
        const float* wc = g_Wc + lid * NI;
#pragma unroll
        for (int m = 0; m < NI / 2; m++) Wc2[m] = pk2(wc[2 * m], wc[2 * m + 1]);
    }
    const u64   cb2   = pk2(g_cbias[lid], 0.0f);   // bias folded into an acc seed
    const float invt  = 1.0f / tau[lid];
    const float alpha = 1.0f - invt;               // h' = alpha*h + invt*z
    const float bo    = b_out[0];
    sh_wo[ch][lid] = W_out[lid];

    const float4* xg = (const float4*)(x + (size_t)b * SEQ * NI);  // 256 float4/chunk
    float* outb = out + (size_t)b * SEQ;

    float4 pf[4];
#pragma unroll
    for (int q = 0; q < 4; q++) pf[q] = xg[q * 64 + lid];

    float h = 0.f, th = 0.f;

#pragma unroll 1
    for (int c = 0; c < NC; c++) {
        // Commit prefetched x chunk; seed ring row 0; prefetch next chunk.
#pragma unroll
        for (int q = 0; q < 4; q++) ((float4*)sh_x[ch])[q * 64 + lid] = pf[q];
        sh_th[ch][lid] = th;
        if (c + 1 < NC) {
#pragma unroll
            for (int q = 0; q < 4; q++) pf[q] = xg[(c + 1) * 256 + q * 64 + lid];
        }
        chain_bar(ch);   // sh_x / ring row 0 / sh_wo visible within this chain

        // x-projection partial for tt = 0 (off the h-dependency chain)
        u64 xz0 = cb2, xz1 = 0ull;
        {
            const ulonglong2* x2 = (const ulonglong2*)(sh_x[ch]);
#pragma unroll
            for (int m = 0; m < 8; m++) {
                ulonglong2 v = x2[m];
                xz0 = fma2(v.x, Wc2[2 * m + 0], xz0);
                xz1 = fma2(v.y, Wc2[2 * m + 1], xz1);
            }
        }

#pragma unroll 1
        for (int tt = 0; tt < TC; tt++) {
            chain_bar(ch);   // ring row tt visible to both warps of this chain

            // hh dot: 64 terms = 32 FFMA2, 4 accumulator chains, x+bias folded in
            u64 a0 = xz0, a1 = xz1, a2 = 0ull, a3 = 0ull;
            const ulonglong2* t2 = (const ulonglong2*)(sh_th[ch] + tt * RS);
#pragma unroll
            for (int m = 0; m < 16; m += 2) {
                ulonglong2 v = t2[m];
                ulonglong2 w = t2[m + 1];
                a0 = fma2(v.x, Whh2[2 * m + 0], a0);
                a1 = fma2(v.y, Whh2[2 * m + 1], a1);
                a2 = fma2(w.x, Whh2[2 * m + 2], a2);
                a3 = fma2(w.y, Whh2[2 * m + 3], a3);
            }
            a0 = add2(a0, a1); a2 = add2(a2, a3); a0 = add2(a0, a2);
            float2 f = upk2(a0);
            const float z = f.x + f.y;

            h  = fmaf(h, alpha, z * invt);             // Euler step (dt = 1)
            th = tanh_fast(h);                         // MUFU.TANH
            sh_th[ch][(tt + 1) * RS + lid] = th;       // fresh row, no WAR

            // Shadow x-projection for tt+1 (tt=TC-1 reads spare row; discarded)
            const ulonglong2* nx2 = (const ulonglong2*)(sh_x[ch] + (tt + 1) * NI);
            xz0 = cb2; xz1 = 0ull;
#pragma unroll
            for (int m = 0; m < 8; m++) {
                ulonglong2 v = nx2[m];
                xz0 = fma2(v.x, Wc2[2 * m + 0], xz0);
                xz1 = fma2(v.y, Wc2[2 * m + 1], xz1);
            }
        }
        chain_bar(ch);   // ring rows 1..TC complete

        // Output head, batched: thread tt<TC computes out[c*TC+tt] from the
        // tanh ring (approx-tanh values; error ~1e-5-level at these |h|).
        if (lid < TC) {
            const float* row = sh_th[ch] + (lid + 1) * RS;
            const float* wo  = sh_wo[ch];
            float o0 = bo, o1 = 0.f, o2 = 0.f, o3 = 0.f;
#pragma unroll
            for (int k = 0; k < NH; k += 4) {
                o0 += row[k + 0] * wo[k + 0];
                o1 += row[k + 1] * wo[k + 1];
                o2 += row[k + 2] * wo[k + 2];
                o3 += row[k + 3] * wo[k + 3];
            }
            outb[c * TC + lid] = (o0 + o1) + (o2 + o3);
        }
        // No trailing barrier: next chunk's pre-barrier writes touch only sh_x
        // and ring row 0; the head reads rows 1..TC, ordered by the next
        // chain_bar before any step overwrites them.
    }
}

extern "C" void kernel_launch(void* const* d_in, const int* in_sizes, int n_in,
                              void* d_out, int out_size)
{
    const float* x     = (const float*)d_in[0];
    const float* W_in  = (const float*)d_in[1];
    const float* b_in  = (const float*)d_in[2];
    const float* W_hh  = (const float*)d_in[3];
    const float* W_ih  = (const float*)d_in[4];
    const float* bias  = (const float*)d_in[5];
    const float* tau   = (const float*)d_in[6];
    const float* W_out = (const float*)d_in[7];
    const float* b_out = (const float*)d_in[8];
    float* out = (float*)d_out;

    precompute_kernel<<<1, 64>>>(W_in, b_in, W_ih, bias);
    lnn_scan_kernel<<<NB / 2, 128>>>(x, W_hh, tau, W_out, b_out, out);
}